// round 14
// baseline (speedup 1.0000x reference)
#include <cuda_runtime.h>
#include <cuda_bf16.h>
#include <math.h>
#include <stdint.h>

// ----------------------------------------------------------------------------
// Attention_13314398617962   (t=512, b=64, s=1024, hu=1024)
// ----------------------------------------------------------------------------

#define T_DIM 512
#define B_DIM 64
#define HU 1024
#define NROWS (T_DIM * B_DIM)   // 32768
#define RPB 16                  // rows per block in score kernel
#define NBLK (NROWS / RPB)      // 2048
#define SLOT 6                  // padded floats per partial (5 + 1)

// dynamic smem: red[RPB][2 jg][128 partials][SLOT] = 24576 floats (96 KB)
#define RED_FLOATS (RPB * 2 * 128 * SLOT)
#define DYN_BYTES  (RED_FLOATS * 4)

__device__ float g_pre0[B_DIM * 10];   // si @ W0[:1024] per b (raw dot)
__device__ float g_ep[30];             // s0[10] t0[10] s1[5] t1[5]
__device__ float g_scores[T_DIM];      // raw scores for rows < 512
__device__ float g_w[T_DIM];           // softmax weights
__device__ float g_bmax[NBLK];
__device__ float g_bsum[NBLK];

// ---------------------------------------------------------------------------
__device__ __forceinline__ void ffma2(unsigned long long& d,
                                      unsigned long long a,
                                      unsigned long long b)
{
    asm("fma.rn.f32x2 %0, %1, %2, %0;" : "+l"(d) : "l"(a), "l"(b));
}
__device__ __forceinline__ void fmul2(unsigned long long& d,
                                      unsigned long long a,
                                      unsigned long long b)
{
    asm("mul.rn.f32x2 %0, %1, %2;" : "=l"(d) : "l"(a), "l"(b));
}
__device__ __forceinline__ unsigned long long pack2(float x)
{
    unsigned long long r;
    asm("mov.b64 %0, {%1, %1};" : "=l"(r) : "f"(x));
    return r;
}
__device__ __forceinline__ unsigned long long packpair(float a, float b)
{
    unsigned long long r;
    asm("mov.b64 %0, {%1, %2};" : "=l"(r) : "f"(a), "f"(b));
    return r;
}
__device__ __forceinline__ void unpack2(unsigned long long v, float& lo, float& hi)
{
    asm("mov.b64 {%0, %1}, %2;" : "=f"(lo), "=f"(hi) : "l"(v));
}

// ---------------------------------------------------------------------------
// K0: per-b si contribution (coalesced W0 reads) + folded BN constants.
// ---------------------------------------------------------------------------
__global__ __launch_bounds__(256)
void prep_kernel(const float* __restrict__ si,
                 const float* __restrict__ W0,
                 const float* __restrict__ b0,
                 const float* __restrict__ g0,
                 const float* __restrict__ be0,
                 const float* __restrict__ m0,
                 const float* __restrict__ v0,
                 const float* __restrict__ b1,
                 const float* __restrict__ g1,
                 const float* __restrict__ be1,
                 const float* __restrict__ m1,
                 const float* __restrict__ v1)
{
    __shared__ float red[64][10];

    int b = blockIdx.x;
    int tid = threadIdx.x;
    int lane = tid & 31;
    int warp = tid >> 5;

    float wv[40];
    {
        const float4* wp = reinterpret_cast<const float4*>(W0 + 4 * tid * 10);
#pragma unroll
        for (int i = 0; i < 10; ++i)
            reinterpret_cast<float4*>(wv)[i] = wp[i];
    }
    float4 sv = reinterpret_cast<const float4*>(si + b * 1024)[tid];

    float pj[10];
#pragma unroll
    for (int j = 0; j < 10; ++j) {
        float a = sv.x * wv[j];
        a = fmaf(sv.y, wv[10 + j], a);
        a = fmaf(sv.z, wv[20 + j], a);
        a = fmaf(sv.w, wv[30 + j], a);
        pj[j] = a;
    }
#pragma unroll
    for (int j = 0; j < 10; ++j) {
        pj[j] += __shfl_xor_sync(0xffffffffu, pj[j], 16);
        pj[j] += __shfl_xor_sync(0xffffffffu, pj[j], 8);
    }
    if (lane < 8) {
#pragma unroll
        for (int j = 0; j < 10; ++j) red[warp * 8 + lane][j] = pj[j];
    }
    __syncthreads();

    if (tid < 10) {
        float s = 0.f;
#pragma unroll
        for (int q = 0; q < 64; ++q) s += red[q][tid];
        g_pre0[b * 10 + tid] = s;
    }

    if (b == 0) {
        if (tid >= 32 && tid < 42) {
            int i = tid - 32;
            float s = g0[i] * (1.0f / sqrtf(v0[i] + 1e-5f));
            g_ep[i] = s;
            g_ep[10 + i] = (b0[i] - m0[i]) * s + be0[i];
        } else if (tid >= 64 && tid < 69) {
            int i = tid - 64;
            float s = g1[i] * (1.0f / sqrtf(v1[i] + 1e-5f));
            g_ep[20 + i] = s;
            g_ep[25 + i] = (b1[i] - m1[i]) * s + be1[i];
        }
    }
}

// ---------------------------------------------------------------------------
// K1: scores + per-block online softmax stats. 16 rows/block, 2048 blocks.
// QUADRANT SPLIT: 512 threads = 4 groups of 128: kg = k-half, jg = j-half.
// Thread owns (4 k in its half) x (5 j) = 20 weight floats (8 u64 + 4 f32
// = 20 regs). Total ~55-60 regs -> __launch_bounds__(512,2) = 32 warps/SM
// (2x prior occupancy), NO spills. jg pairs read identical h lines (L1
// MSHR-merged; DRAM traffic unchanged). Ring-2 float4 prefetch -> 32 KB/SM
// in flight. Per warp-row: 1 LDG.128, 8 FFMA2 + 4 FFMA, 5 SHFL (one xor-16
// round), 3 STS.64 (lane<16).
// ---------------------------------------------------------------------------
__global__ __launch_bounds__(512, 2)
void score_kernel(const float* __restrict__ h,
                  const float* __restrict__ W0,
                  const float* __restrict__ W1,
                  const float* __restrict__ W2,
                  const float* __restrict__ b2)
{
    extern __shared__ float red[];            // [it][jg][part128][SLOT] 96 KB

    __shared__ float pre0s[RPB * 10];
    __shared__ float dsum[RPB * 10];
    __shared__ float epi[86];                 // s0 t0 s1 t1 W1[50] W2[5] b2

    int tid  = threadIdx.x;
    int lane = tid & 31;
    int kg   = (tid >> 7) & 1;                // k-half 0/1
    int jg   = tid >> 8;                      // j-half 0/1
    int ts   = tid & 127;                     // thread within k-group
    int wl   = (tid >> 5) & 3;                // warp within (kg,jg) group
    int rowbase = blockIdx.x * RPB;
    int bbase   = rowbase & 63;

    if (tid < 30)                  epi[tid] = g_ep[tid];
    if (tid >= 32 && tid < 82)     epi[30 + tid - 32] = W1[tid - 32];
    if (tid >= 96 && tid < 101)    epi[80 + tid - 96] = W2[tid - 96];
    if (tid == 101)                epi[85] = b2[0];
    if (tid < RPB * 10)            pre0s[tid] = g_pre0[bbase * 10 + tid];

    // 20 weight floats: rows 1024 + kg*512 + 4*ts + kk, cols jg*5 .. +4
    unsigned long long u[8];
    float ws[4];
    {
        const float* wb = W0 + (size_t)(1024 + kg * 512 + 4 * ts) * 10 + jg * 5;
#pragma unroll
        for (int kk = 0; kk < 4; ++kk) {
            float f0 = wb[kk * 10 + 0];
            float f1 = wb[kk * 10 + 1];
            float f2 = wb[kk * 10 + 2];
            float f3 = wb[kk * 10 + 3];
            ws[kk]   = wb[kk * 10 + 4];
            u[2 * kk + 0] = packpair(f0, f1);
            u[2 * kk + 1] = packpair(f2, f3);
        }
    }

    const float* hb = h + (size_t)rowbase * 1024 + kg * 512 + 4 * ts;
    float4 P[2];
    P[0] = *reinterpret_cast<const float4*>(hb);
    P[1] = *reinterpret_cast<const float4*>(hb + 1024);

    __syncthreads();   // smem staging visible

    // partial slot: per (row,jg): pidx = kg*64 + wl*16 + lane(<16)
    float* myred = red + ((0 * 2 + jg) * 128 + kg * 64 + wl * 16 + lane) * SLOT;

#pragma unroll
    for (int it = 0; it < RPB; ++it) {
        float4 cv = P[it & 1];
        if (it < RPB - 2)
            P[it & 1] = *reinterpret_cast<const float4*>(hb + (size_t)(it + 2) * 1024);

        unsigned long long a0, a1;
        float a2;
        unsigned long long hh;
        hh = pack2(cv.x);
        fmul2(a0, hh, u[0]); fmul2(a1, hh, u[1]); a2 = cv.x * ws[0];
        hh = pack2(cv.y);
        ffma2(a0, hh, u[2]); ffma2(a1, hh, u[3]); a2 = fmaf(cv.y, ws[1], a2);
        hh = pack2(cv.z);
        ffma2(a0, hh, u[4]); ffma2(a1, hh, u[5]); a2 = fmaf(cv.z, ws[2], a2);
        hh = pack2(cv.w);
        ffma2(a0, hh, u[6]); ffma2(a1, hh, u[7]); a2 = fmaf(cv.w, ws[3], a2);

        float p0, p1, p2, p3;
        unpack2(a0, p0, p1);
        unpack2(a1, p2, p3);

        // one shfl round: lanes<16 hold sums over {lane, lane+16}
        p0 += __shfl_xor_sync(0xffffffffu, p0, 16);
        p1 += __shfl_xor_sync(0xffffffffu, p1, 16);
        p2 += __shfl_xor_sync(0xffffffffu, p2, 16);
        p3 += __shfl_xor_sync(0xffffffffu, p3, 16);
        a2 += __shfl_xor_sync(0xffffffffu, a2, 16);

        if (lane < 16) {
            float2* rb = reinterpret_cast<float2*>(myred + it * (2 * 128 * SLOT));
            rb[0] = make_float2(p0, p1);
            rb[1] = make_float2(p2, p3);
            rb[2] = make_float2(a2, 0.f);
        }
    }
    __syncthreads();

    // block reduce: 160 (row,j) sums, each over 128 partials (stride SLOT)
    if (tid < RPB * 10) {
        int rl = tid / 10;
        int j  = tid - rl * 10;
        int jgg = j / 5;
        int jj  = j - jgg * 5;
        const float* base = red + ((rl * 2 + jgg) * 128) * SLOT + jj;
        float s0 = 0.f, s1 = 0.f, s2 = 0.f, s3 = 0.f;
#pragma unroll
        for (int q = 0; q < 32; ++q) {
            s0 += base[(4 * q) * SLOT];
            s1 += base[(4 * q + 1) * SLOT];
            s2 += base[(4 * q + 2) * SLOT];
            s3 += base[(4 * q + 3) * SLOT];
        }
        dsum[tid] = (s0 + s1) + (s2 + s3);
    }
    __syncthreads();

    // fused MLP epilogue (16 rows) + warp-0 online softmax stats
    if (tid < 32) {
        float sc = -1e30f;
        if (tid < RPB) {
            int row = rowbase + tid;
            float x0[10];
#pragma unroll
            for (int j = 0; j < 10; ++j) {
                float d = dsum[tid * 10 + j] + pre0s[tid * 10 + j];
                x0[j] = fmaxf(fmaf(d, epi[j], epi[10 + j]), 0.f);
            }
            sc = epi[85];
#pragma unroll
            for (int i = 0; i < 5; ++i) {
                float z = 0.f;
#pragma unroll
                for (int j = 0; j < 10; ++j)
                    z = fmaf(x0[j], epi[30 + j * 5 + i], z);
                float x1 = fmaxf(fmaf(z, epi[20 + i], epi[25 + i]), 0.f);
                sc = fmaf(x1, epi[80 + i], sc);
            }
            if (row < T_DIM) g_scores[row] = sc;
        }
        float m = sc;
#pragma unroll
        for (int o = 16; o > 0; o >>= 1)
            m = fmaxf(m, __shfl_xor_sync(0xffffffffu, m, o));
        float e = (tid < RPB) ? expf(sc - m) : 0.f;
#pragma unroll
        for (int o = 16; o > 0; o >>= 1)
            e += __shfl_xor_sync(0xffffffffu, e, o);
        if (tid == 0) {
            g_bmax[blockIdx.x] = m;
            g_bsum[blockIdx.x] = e;
        }
    }
}

// ---------------------------------------------------------------------------
// K2: combine 2048 (max, expsum) pairs -> M, S; write 512 weights.
// ---------------------------------------------------------------------------
__global__ void combine_kernel()
{
    __shared__ float sm[512];
    __shared__ float MS[2];
    int tid = threadIdx.x;

    float lm = -1e30f;
    float bm[4];
#pragma unroll
    for (int i = 0; i < 4; ++i) {
        bm[i] = g_bmax[tid * 4 + i];
        lm = fmaxf(lm, bm[i]);
    }
    sm[tid] = lm;
    __syncthreads();
    for (int s = 256; s > 0; s >>= 1) {
        if (tid < s) sm[tid] = fmaxf(sm[tid], sm[tid + s]);
        __syncthreads();
    }
    if (tid == 0) MS[0] = sm[0];
    __syncthreads();
    float M = MS[0];

    float ls = 0.f;
#pragma unroll
    for (int i = 0; i < 4; ++i)
        ls += g_bsum[tid * 4 + i] * expf(bm[i] - M);
    sm[tid] = ls;
    __syncthreads();
    for (int s = 256; s > 0; s >>= 1) {
        if (tid < s) sm[tid] += sm[tid + s];
        __syncthreads();
    }
    if (tid == 0) MS[1] = 1.0f / sm[0];
    __syncthreads();

    g_w[tid] = expf(g_scores[tid] - M) * MS[1];
}

// ---------------------------------------------------------------------------
// K3: ci[b,:] = sum_tau w[tau] * h[tau,b,:]
// grid (8 chunks of 128 cols, 64 b) x 512 threads (16 warps, t == w mod 16).
// (best measured configuration, ~24.4 us)
// ---------------------------------------------------------------------------
__global__ __launch_bounds__(512)
void wsum_kernel(const float* __restrict__ h, float* __restrict__ out)
{
    __shared__ float ws[T_DIM];
    __shared__ float part[16][128];

    int tid  = threadIdx.x;
    int w    = tid >> 5;
    int lane = tid & 31;
    int c = blockIdx.x;           // 128-col chunk
    int b = blockIdx.y;

    if (tid < 128)
        reinterpret_cast<float4*>(ws)[tid] = reinterpret_cast<const float4*>(g_w)[tid];
    __syncthreads();

    const float* hp = h + (size_t)b * 1024 + c * 128 + 4 * lane;
    float4 acc = make_float4(0.f, 0.f, 0.f, 0.f);
#pragma unroll 8
    for (int i = 0; i < T_DIM / 16; ++i) {
        int t = i * 16 + w;
        float4 hv = *reinterpret_cast<const float4*>(hp + (size_t)t * (B_DIM * HU));
        float wv = ws[t];
        acc.x = fmaf(wv, hv.x, acc.x);
        acc.y = fmaf(wv, hv.y, acc.y);
        acc.z = fmaf(wv, hv.z, acc.z);
        acc.w = fmaf(wv, hv.w, acc.w);
    }
    *reinterpret_cast<float4*>(&part[w][4 * lane]) = acc;
    __syncthreads();

    if (tid < 128) {
        float s0 = part[0][tid], s1 = part[1][tid];
        float s2 = part[2][tid], s3 = part[3][tid];
#pragma unroll
        for (int q = 4; q < 16; q += 4) {
            s0 += part[q][tid];
            s1 += part[q + 1][tid];
            s2 += part[q + 2][tid];
            s3 += part[q + 3][tid];
        }
        out[b * 1024 + c * 128 + tid] = (s0 + s1) + (s2 + s3);
    }
}

// ---------------------------------------------------------------------------
extern "C" void kernel_launch(void* const* d_in, const int* in_sizes, int n_in,
                              void* d_out, int out_size)
{
    const float* si  = (const float*)d_in[0];
    const float* h   = (const float*)d_in[1];
    const float* W0  = (const float*)d_in[2];
    const float* b0  = (const float*)d_in[3];
    const float* g0  = (const float*)d_in[4];
    const float* be0 = (const float*)d_in[5];
    const float* m0  = (const float*)d_in[6];
    const float* v0  = (const float*)d_in[7];
    const float* W1  = (const float*)d_in[8];
    const float* b1  = (const float*)d_in[9];
    const float* g1  = (const float*)d_in[10];
    const float* be1 = (const float*)d_in[11];
    const float* m1  = (const float*)d_in[12];
    const float* v1  = (const float*)d_in[13];
    const float* W2  = (const float*)d_in[14];
    const float* b2  = (const float*)d_in[15];
    float* out = (float*)d_out;

    static int smem_set = 0;
    if (!smem_set) {
        cudaFuncSetAttribute(score_kernel,
                             cudaFuncAttributeMaxDynamicSharedMemorySize,
                             DYN_BYTES);
        smem_set = 1;
    }

    prep_kernel<<<B_DIM, 256>>>(si, W0, b0, g0, be0, m0, v0, b1, g1, be1, m1, v1);
    score_kernel<<<NBLK, 512, DYN_BYTES>>>(h, W0, W1, W2, b2);
    combine_kernel<<<1, 512>>>();
    wsum_kernel<<<dim3(8, B_DIM), 512>>>(h, out);
}

// round 15
// speedup vs baseline: 1.5589x; 1.5589x over previous
#include <cuda_runtime.h>
#include <cuda_bf16.h>
#include <math.h>
#include <stdint.h>

// ----------------------------------------------------------------------------
// Attention_13314398617962   (t=512, b=64, s=1024, hu=1024)
//   scores[t,b] = MLP(concat(si[b], h[t,b]))   (2048 -> 10 -> 5 -> 1, BN+relu)
//   a = softmax(scores.flatten())              (over all 32768)
//   ci[b,:] = sum_tau a[tau] * h[tau_t, tau_b, :]   (tau < 512)
// ----------------------------------------------------------------------------

#define T_DIM 512
#define B_DIM 64
#define HU 1024
#define NROWS (T_DIM * B_DIM)   // 32768
#define RPB 16                  // rows per block in score kernel
#define NBLK (NROWS / RPB)      // 2048
#define SLOT 6                  // padded floats per partial (5 + 1)

// dynamic smem: red[RPB][2 jg][64 partials][SLOT] = 12288 floats (48 KB)
#define RED_FLOATS (RPB * 2 * 64 * SLOT)
#define DYN_BYTES  (RED_FLOATS * 4)

__device__ float g_pre0[B_DIM * 10];   // si @ W0[:1024] per b (raw dot)
__device__ float g_ep[30];             // s0[10] t0[10] s1[5] t1[5]
__device__ float g_scores[T_DIM];      // raw scores for rows < 512
__device__ float g_w[T_DIM];           // softmax weights
__device__ float g_bmax[NBLK];
__device__ float g_bsum[NBLK];

// ---------------------------------------------------------------------------
__device__ __forceinline__ void ffma2(unsigned long long& d,
                                      unsigned long long a,
                                      unsigned long long b)
{
    asm("fma.rn.f32x2 %0, %1, %2, %0;" : "+l"(d) : "l"(a), "l"(b));
}
__device__ __forceinline__ void fmul2(unsigned long long& d,
                                      unsigned long long a,
                                      unsigned long long b)
{
    asm("mul.rn.f32x2 %0, %1, %2;" : "=l"(d) : "l"(a), "l"(b));
}
__device__ __forceinline__ unsigned long long pack2(float x)
{
    unsigned long long r;
    asm("mov.b64 %0, {%1, %1};" : "=l"(r) : "f"(x));
    return r;
}
__device__ __forceinline__ unsigned long long packpair(float a, float b)
{
    unsigned long long r;
    asm("mov.b64 %0, {%1, %2};" : "=l"(r) : "f"(a), "f"(b));
    return r;
}
__device__ __forceinline__ void unpack2(unsigned long long v, float& lo, float& hi)
{
    asm("mov.b64 {%0, %1}, %2;" : "=f"(lo), "=f"(hi) : "l"(v));
}

// ---------------------------------------------------------------------------
// K0: per-b si contribution (coalesced W0 reads) + folded BN constants.
// ---------------------------------------------------------------------------
__global__ __launch_bounds__(256)
void prep_kernel(const float* __restrict__ si,
                 const float* __restrict__ W0,
                 const float* __restrict__ b0,
                 const float* __restrict__ g0,
                 const float* __restrict__ be0,
                 const float* __restrict__ m0,
                 const float* __restrict__ v0,
                 const float* __restrict__ b1,
                 const float* __restrict__ g1,
                 const float* __restrict__ be1,
                 const float* __restrict__ m1,
                 const float* __restrict__ v1)
{
    __shared__ float red[64][10];

    int b = blockIdx.x;
    int tid = threadIdx.x;
    int lane = tid & 31;
    int warp = tid >> 5;

    float wv[40];
    {
        const float4* wp = reinterpret_cast<const float4*>(W0 + 4 * tid * 10);
#pragma unroll
        for (int i = 0; i < 10; ++i)
            reinterpret_cast<float4*>(wv)[i] = wp[i];
    }
    float4 sv = reinterpret_cast<const float4*>(si + b * 1024)[tid];

    float pj[10];
#pragma unroll
    for (int j = 0; j < 10; ++j) {
        float a = sv.x * wv[j];
        a = fmaf(sv.y, wv[10 + j], a);
        a = fmaf(sv.z, wv[20 + j], a);
        a = fmaf(sv.w, wv[30 + j], a);
        pj[j] = a;
    }
#pragma unroll
    for (int j = 0; j < 10; ++j) {
        pj[j] += __shfl_xor_sync(0xffffffffu, pj[j], 16);
        pj[j] += __shfl_xor_sync(0xffffffffu, pj[j], 8);
    }
    if (lane < 8) {
#pragma unroll
        for (int j = 0; j < 10; ++j) red[warp * 8 + lane][j] = pj[j];
    }
    __syncthreads();

    if (tid < 10) {
        float s = 0.f;
#pragma unroll
        for (int q = 0; q < 64; ++q) s += red[q][tid];
        g_pre0[b * 10 + tid] = s;
    }

    if (b == 0) {
        if (tid >= 32 && tid < 42) {
            int i = tid - 32;
            float s = g0[i] * (1.0f / sqrtf(v0[i] + 1e-5f));
            g_ep[i] = s;
            g_ep[10 + i] = (b0[i] - m0[i]) * s + be0[i];
        } else if (tid >= 64 && tid < 69) {
            int i = tid - 64;
            float s = g1[i] * (1.0f / sqrtf(v1[i] + 1e-5f));
            g_ep[20 + i] = s;
            g_ep[25 + i] = (b1[i] - m1[i]) * s + be1[i];
        }
    }
}

// ---------------------------------------------------------------------------
// K1: scores + per-block online softmax stats. 16 rows/block, 2048 blocks.
// j-SPLIT @ 256 threads: 2 j-groups x 128 threads; thread ts owns the FULL
// row's k = 4*ts..+3 AND 512+4*ts..+3 (8 k), and outputs j = jg*5..jg*5+4
// only -> 40 weight floats (16 u64 + 8 f32 regs, HALF of R12).
// Ring-2 pair prefetch (16 regs); total ~81 regs -> fits the 85-reg cap of
// __launch_bounds__(256,3) = 24 warps/SM (1.5x R12's occupancy), no spills.
// jg pairs read identical h lines (L1-merged; unique DRAM stream unchanged).
// Per warp-row: 2 LDG.128, 16 FFMA2 + 8 FFMA, 5 SHFL, 3 STS.64 (lane<16).
// red = 48 KB dynamic smem -> 3 CTAs/SM = 144 KB.
// ---------------------------------------------------------------------------
__global__ __launch_bounds__(256, 3)
void score_kernel(const float* __restrict__ h,
                  const float* __restrict__ W0,
                  const float* __restrict__ W1,
                  const float* __restrict__ W2,
                  const float* __restrict__ b2)
{
    extern __shared__ float red[];            // [it][jg][part64][SLOT] 48 KB

    __shared__ float pre0s[RPB * 10];
    __shared__ float dsum[RPB * 10];
    __shared__ float epi[86];                 // s0 t0 s1 t1 W1[50] W2[5] b2

    int tid  = threadIdx.x;
    int lane = tid & 31;
    int jg   = tid >> 7;                      // j-half 0/1
    int ts   = tid & 127;                     // thread within j-group
    int wl   = (tid >> 5) & 3;                // warp within j-group
    int rowbase = blockIdx.x * RPB;
    int bbase   = rowbase & 63;

    if (tid < 30)                  epi[tid] = g_ep[tid];
    if (tid >= 32 && tid < 82)     epi[30 + tid - 32] = W1[tid - 32];
    if (tid >= 96 && tid < 101)    epi[80 + tid - 96] = W2[tid - 96];
    if (tid == 101)                epi[85] = b2[0];
    if (tid < RPB * 10)            pre0s[tid] = g_pre0[bbase * 10 + tid];

    // 40 weight floats (8 k x 5 j): per k, 2 u64 (j0..j3) + 1 f32 (j4)
    unsigned long long u[16];
    float w4[8];
    {
        const float* wb0 = W0 + (size_t)(1024 + 4 * ts) * 10 + jg * 5;        // k lo
        const float* wb1 = W0 + (size_t)(1024 + 512 + 4 * ts) * 10 + jg * 5;  // k hi
#pragma unroll
        for (int kk = 0; kk < 4; ++kk) {
            u[2 * kk + 0] = packpair(wb0[kk * 10 + 0], wb0[kk * 10 + 1]);
            u[2 * kk + 1] = packpair(wb0[kk * 10 + 2], wb0[kk * 10 + 3]);
            w4[kk]        = wb0[kk * 10 + 4];
            u[8 + 2 * kk + 0] = packpair(wb1[kk * 10 + 0], wb1[kk * 10 + 1]);
            u[8 + 2 * kk + 1] = packpair(wb1[kk * 10 + 2], wb1[kk * 10 + 3]);
            w4[4 + kk]        = wb1[kk * 10 + 4];
        }
    }

    const float* hb = h + (size_t)rowbase * 1024 + 4 * ts;
    float4 PA[2], PB[2];
#pragma unroll
    for (int i = 0; i < 2; ++i) {
        PA[i] = *reinterpret_cast<const float4*>(hb + (size_t)i * 1024);
        PB[i] = *reinterpret_cast<const float4*>(hb + (size_t)i * 1024 + 512);
    }

    __syncthreads();   // smem staging visible

    // partial slot per (row,jg): pidx = wl*16 + lane(<16)
    float* myred = red + (jg * 64 + wl * 16 + lane) * SLOT;

#pragma unroll
    for (int it = 0; it < RPB; ++it) {
        float4 ca = PA[it & 1];
        float4 cb = PB[it & 1];
        if (it < RPB - 2) {
            const float* pn = hb + (size_t)(it + 2) * 1024;
            PA[it & 1] = *reinterpret_cast<const float4*>(pn);
            PB[it & 1] = *reinterpret_cast<const float4*>(pn + 512);
        }

        unsigned long long a0, a1;
        float a2;
        unsigned long long hh;
        hh = pack2(ca.x);
        fmul2(a0, hh, u[0]); fmul2(a1, hh, u[1]); a2 = ca.x * w4[0];
        hh = pack2(ca.y);
        ffma2(a0, hh, u[2]); ffma2(a1, hh, u[3]); a2 = fmaf(ca.y, w4[1], a2);
        hh = pack2(ca.z);
        ffma2(a0, hh, u[4]); ffma2(a1, hh, u[5]); a2 = fmaf(ca.z, w4[2], a2);
        hh = pack2(ca.w);
        ffma2(a0, hh, u[6]); ffma2(a1, hh, u[7]); a2 = fmaf(ca.w, w4[3], a2);
        hh = pack2(cb.x);
        ffma2(a0, hh, u[8]); ffma2(a1, hh, u[9]); a2 = fmaf(cb.x, w4[4], a2);
        hh = pack2(cb.y);
        ffma2(a0, hh, u[10]); ffma2(a1, hh, u[11]); a2 = fmaf(cb.y, w4[5], a2);
        hh = pack2(cb.z);
        ffma2(a0, hh, u[12]); ffma2(a1, hh, u[13]); a2 = fmaf(cb.z, w4[6], a2);
        hh = pack2(cb.w);
        ffma2(a0, hh, u[14]); ffma2(a1, hh, u[15]); a2 = fmaf(cb.w, w4[7], a2);

        float p0, p1, p2, p3;
        unpack2(a0, p0, p1);
        unpack2(a1, p2, p3);

        // one shfl round: lanes<16 hold sums over {lane, lane+16}
        p0 += __shfl_xor_sync(0xffffffffu, p0, 16);
        p1 += __shfl_xor_sync(0xffffffffu, p1, 16);
        p2 += __shfl_xor_sync(0xffffffffu, p2, 16);
        p3 += __shfl_xor_sync(0xffffffffu, p3, 16);
        a2 += __shfl_xor_sync(0xffffffffu, a2, 16);

        if (lane < 16) {
            float2* rb = reinterpret_cast<float2*>(myred + it * (2 * 64 * SLOT));
            rb[0] = make_float2(p0, p1);
            rb[1] = make_float2(p2, p3);
            rb[2] = make_float2(a2, 0.f);
        }
    }
    __syncthreads();

    // block reduce: 160 (row,j) sums, each over 64 partials (stride SLOT)
    if (tid < RPB * 10) {
        int rl = tid / 10;
        int j  = tid - rl * 10;
        int jgg = j / 5;
        int jj  = j - jgg * 5;
        const float* base = red + ((rl * 2 + jgg) * 64) * SLOT + jj;
        float s0 = 0.f, s1 = 0.f, s2 = 0.f, s3 = 0.f;
#pragma unroll
        for (int q = 0; q < 16; ++q) {
            s0 += base[(4 * q) * SLOT];
            s1 += base[(4 * q + 1) * SLOT];
            s2 += base[(4 * q + 2) * SLOT];
            s3 += base[(4 * q + 3) * SLOT];
        }
        dsum[tid] = (s0 + s1) + (s2 + s3);
    }
    __syncthreads();

    // fused MLP epilogue (16 rows) + warp-0 online softmax stats
    if (tid < 32) {
        float sc = -1e30f;
        if (tid < RPB) {
            int row = rowbase + tid;
            float x0[10];
#pragma unroll
            for (int j = 0; j < 10; ++j) {
                float d = dsum[tid * 10 + j] + pre0s[tid * 10 + j];
                x0[j] = fmaxf(fmaf(d, epi[j], epi[10 + j]), 0.f);
            }
            sc = epi[85];
#pragma unroll
            for (int i = 0; i < 5; ++i) {
                float z = 0.f;
#pragma unroll
                for (int j = 0; j < 10; ++j)
                    z = fmaf(x0[j], epi[30 + j * 5 + i], z);
                float x1 = fmaxf(fmaf(z, epi[20 + i], epi[25 + i]), 0.f);
                sc = fmaf(x1, epi[80 + i], sc);
            }
            if (row < T_DIM) g_scores[row] = sc;
        }
        float m = sc;
#pragma unroll
        for (int o = 16; o > 0; o >>= 1)
            m = fmaxf(m, __shfl_xor_sync(0xffffffffu, m, o));
        float e = (tid < RPB) ? expf(sc - m) : 0.f;
#pragma unroll
        for (int o = 16; o > 0; o >>= 1)
            e += __shfl_xor_sync(0xffffffffu, e, o);
        if (tid == 0) {
            g_bmax[blockIdx.x] = m;
            g_bsum[blockIdx.x] = e;
        }
    }
}

// ---------------------------------------------------------------------------
// K2: combine 2048 (max, expsum) pairs -> M, S; write 512 weights.
// ---------------------------------------------------------------------------
__global__ void combine_kernel()
{
    __shared__ float sm[512];
    __shared__ float MS[2];
    int tid = threadIdx.x;

    float lm = -1e30f;
    float bm[4];
#pragma unroll
    for (int i = 0; i < 4; ++i) {
        bm[i] = g_bmax[tid * 4 + i];
        lm = fmaxf(lm, bm[i]);
    }
    sm[tid] = lm;
    __syncthreads();
    for (int s = 256; s > 0; s >>= 1) {
        if (tid < s) sm[tid] = fmaxf(sm[tid], sm[tid + s]);
        __syncthreads();
    }
    if (tid == 0) MS[0] = sm[0];
    __syncthreads();
    float M = MS[0];

    float ls = 0.f;
#pragma unroll
    for (int i = 0; i < 4; ++i)
        ls += g_bsum[tid * 4 + i] * expf(bm[i] - M);
    sm[tid] = ls;
    __syncthreads();
    for (int s = 256; s > 0; s >>= 1) {
        if (tid < s) sm[tid] += sm[tid + s];
        __syncthreads();
    }
    if (tid == 0) MS[1] = 1.0f / sm[0];
    __syncthreads();

    g_w[tid] = expf(g_scores[tid] - M) * MS[1];
}

// ---------------------------------------------------------------------------
// K3: ci[b,:] = sum_tau w[tau] * h[tau,b,:]
// grid (8 chunks of 128 cols, 64 b) x 512 threads (16 warps, t == w mod 16).
// (best measured configuration, ~24.4 us)
// ---------------------------------------------------------------------------
__global__ __launch_bounds__(512)
void wsum_kernel(const float* __restrict__ h, float* __restrict__ out)
{
    __shared__ float ws[T_DIM];
    __shared__ float part[16][128];

    int tid  = threadIdx.x;
    int w    = tid >> 5;
    int lane = tid & 31;
    int c = blockIdx.x;           // 128-col chunk
    int b = blockIdx.y;

    if (tid < 128)
        reinterpret_cast<float4*>(ws)[tid] = reinterpret_cast<const float4*>(g_w)[tid];
    __syncthreads();

    const float* hp = h + (size_t)b * 1024 + c * 128 + 4 * lane;
    float4 acc = make_float4(0.f, 0.f, 0.f, 0.f);
#pragma unroll 8
    for (int i = 0; i < T_DIM / 16; ++i) {
        int t = i * 16 + w;
        float4 hv = *reinterpret_cast<const float4*>(hp + (size_t)t * (B_DIM * HU));
        float wv = ws[t];
        acc.x = fmaf(wv, hv.x, acc.x);
        acc.y = fmaf(wv, hv.y, acc.y);
        acc.z = fmaf(wv, hv.z, acc.z);
        acc.w = fmaf(wv, hv.w, acc.w);
    }
    *reinterpret_cast<float4*>(&part[w][4 * lane]) = acc;
    __syncthreads();

    if (tid < 128) {
        float s0 = part[0][tid], s1 = part[1][tid];
        float s2 = part[2][tid], s3 = part[3][tid];
#pragma unroll
        for (int q = 4; q < 16; q += 4) {
            s0 += part[q][tid];
            s1 += part[q + 1][tid];
            s2 += part[q + 2][tid];
            s3 += part[q + 3][tid];
        }
        out[b * 1024 + c * 128 + tid] = (s0 + s1) + (s2 + s3);
    }
}

// ---------------------------------------------------------------------------
extern "C" void kernel_launch(void* const* d_in, const int* in_sizes, int n_in,
                              void* d_out, int out_size)
{
    const float* si  = (const float*)d_in[0];
    const float* h   = (const float*)d_in[1];
    const float* W0  = (const float*)d_in[2];
    const float* b0  = (const float*)d_in[3];
    const float* g0  = (const float*)d_in[4];
    const float* be0 = (const float*)d_in[5];
    const float* m0  = (const float*)d_in[6];
    const float* v0  = (const float*)d_in[7];
    const float* W1  = (const float*)d_in[8];
    const float* b1  = (const float*)d_in[9];
    const float* g1  = (const float*)d_in[10];
    const float* be1 = (const float*)d_in[11];
    const float* m1  = (const float*)d_in[12];
    const float* v1  = (const float*)d_in[13];
    const float* W2  = (const float*)d_in[14];
    const float* b2  = (const float*)d_in[15];
    float* out = (float*)d_out;

    static int smem_set = 0;
    if (!smem_set) {
        cudaFuncSetAttribute(score_kernel,
                             cudaFuncAttributeMaxDynamicSharedMemorySize,
                             DYN_BYTES);
        smem_set = 1;
    }

    prep_kernel<<<B_DIM, 256>>>(si, W0, b0, g0, be0, m0, v0, b1, g1, be1, m1, v1);
    score_kernel<<<NBLK, 256, DYN_BYTES>>>(h, W0, W1, W2, b2);
    combine_kernel<<<1, 512>>>();
    wsum_kernel<<<dim3(8, B_DIM), 512>>>(h, out);
}